// round 5
// baseline (speedup 1.0000x reference)
#include <cuda_runtime.h>

#define NN 20000
#define MP 20096
#define EE 50000
#define GG 128
#define NBLK 157   // ceil(NN/128) for BN partials

// ---------- device-global scratch (allocation-free rule) ----------
__device__ float g_h1[(size_t)EE * 128];
__device__ float g_h2[(size_t)EE * 256];
__device__ float g_M1[(size_t)MP * 4096];
__device__ float g_M2[(size_t)MP * 16384];
__device__ float g_B1[4096 * 64];
__device__ float g_B2[16384 * 64];
__device__ float g_S1[(size_t)MP * 64];
__device__ float g_S2[(size_t)MP * 64];
__device__ float g_Xs[NN * 32];
__device__ float g_Hs[NN * 64];
__device__ float g_out1[(size_t)NN * 64];
__device__ float g_hnode[(size_t)NN * 64];
__device__ float g_out2[(size_t)NN * 64];
__device__ int   g_deg[NN];
__device__ int   g_cursor[NN];
__device__ int   g_rowptr[NN];
__device__ int   g_elist[EE];
__device__ float g_bnp[NBLK * 64];
__device__ float g_bnp2[NBLK * 64];
__device__ float g_coef[4 * 64];     // sc1, sh1, sc2, sh2
__device__ float g_pool[GG * 64];
__device__ float g_pcnt[GG];

__global__ void k_zero() {
    int i = blockIdx.x * blockDim.x + threadIdx.x;
    if (i < NN) { g_deg[i] = 0; g_cursor[i] = 0; }
}

// ---------- edge MLP hidden: h = relu(ea @ w1 + b1) ----------
template <int SLOT>
__global__ void k_edge_mlp(const float* __restrict__ ea, const float* __restrict__ w,
                           const float* __restrict__ b) {
    constexpr int KD = (SLOT == 0) ? 128 : 256;
    float* out = (SLOT == 0) ? g_h1 : g_h2;
    int e = blockIdx.x, t = threadIdx.x;
    float acc = __ldg(&b[t]);
#pragma unroll
    for (int c = 0; c < 8; c++)
        acc = fmaf(__ldg(&ea[e * 8 + c]), __ldg(&w[c * KD + t]), acc);
    out[(size_t)e * KD + t] = fmaxf(acc, 0.f);
}

// ---------- reshape w2 -> B[(i*KD+k)*64 + o] ----------
__global__ void k_reshapeB1(const float* __restrict__ w2) {
    int idx = blockIdx.x * blockDim.x + threadIdx.x;
    if (idx < 4096 * 64) {
        int o = idx & 63, r = idx >> 6, k = r & 127, i = r >> 7;
        g_B1[idx] = w2[k * 2048 + i * 64 + o];
    }
}
__global__ void k_reshapeB2(const float* __restrict__ w2) {
    int idx = blockIdx.x * blockDim.x + threadIdx.x;
    if (idx < 16384 * 64) {
        int o = idx & 63, r = idx >> 6, k = r & 255, i = r >> 8;
        g_B2[idx] = w2[k * 4096 + i * 64 + o];
    }
}

// ---------- CSR over dst ----------
__global__ void k_count(const int* __restrict__ dst) {
    int e = blockIdx.x * blockDim.x + threadIdx.x;
    if (e < EE) atomicAdd(&g_deg[dst[e]], 1);
}

__global__ void k_scan() {   // 1 block, 1024 threads, 20 items/thread
    __shared__ int part[1024];
    int t = threadIdx.x;
    const int IT = 20;
    int base = t * IT, loc[IT], s = 0;
#pragma unroll
    for (int i = 0; i < IT; i++) {
        int idx = base + i;
        int v = (idx < NN) ? g_deg[idx] : 0;
        loc[i] = s; s += v;
    }
    part[t] = s;
    __syncthreads();
    for (int off = 1; off < 1024; off <<= 1) {
        int v = (t >= off) ? part[t - off] : 0;
        __syncthreads();
        part[t] += v;
        __syncthreads();
    }
    int prev = (t == 0) ? 0 : part[t - 1];
#pragma unroll
    for (int i = 0; i < IT; i++) {
        int idx = base + i;
        if (idx < NN) g_rowptr[idx] = prev + loc[i];
    }
}

__global__ void k_fill(const int* __restrict__ dst) {
    int e = blockIdx.x * blockDim.x + threadIdx.x;
    if (e < EE) {
        int d = dst[e];
        int p = atomicAdd(&g_cursor[d], 1);
        g_elist[g_rowptr[d] + p] = e;
    }
}

// ---------- M[n, i*KD+k] = sum_e h[e,k]*feat[src,i];  Fs[n,i] = sum_e feat[src,i] ----------
template <int SLOT>
__global__ void k_buildM(const float* __restrict__ feat_in, const int* __restrict__ src) {
    constexpr int CIN = (SLOT == 0) ? 32 : 64;
    constexpr int KD  = (SLOT == 0) ? 128 : 256;
    const float* __restrict__ h    = (SLOT == 0) ? g_h1 : g_h2;
    const float* __restrict__ feat = (SLOT == 0) ? feat_in : g_hnode;
    float* __restrict__ M  = (SLOT == 0) ? g_M1 : g_M2;
    float* __restrict__ Fs = (SLOT == 0) ? g_Xs : g_Hs;
    int n = blockIdx.x, t = threadIdx.x;   // t = k
    int beg = g_rowptr[n], end = beg + g_deg[n];
    float acc[CIN];
#pragma unroll
    for (int i = 0; i < CIN; i++) acc[i] = 0.f;
    float fsum = 0.f;
    for (int p = beg; p < end; p++) {
        int e = g_elist[p];
        const float* fr = feat + (size_t)src[e] * CIN;
        float hk = h[(size_t)e * KD + t];
#pragma unroll
        for (int i = 0; i < CIN; i++) acc[i] = fmaf(hk, __ldg(&fr[i]), acc[i]);
        if (t < CIN) fsum += __ldg(&fr[t]);
    }
    float* Mrow = M + (size_t)n * (CIN * KD);
#pragma unroll
    for (int i = 0; i < CIN; i++) Mrow[i * KD + t] = acc[i];
    if (t < CIN) Fs[n * CIN + t] = fsum;
}

// ---------- GEMM: C[MP,64] = A[MP,K] @ B[K,64].  BM=64 BN=64 BK=16, 256 thr, 4x4 micro ----------
template <int SLOT>
__global__ void __launch_bounds__(256) k_gemm() {
    constexpr int K = (SLOT == 0) ? 4096 : 16384;
    const float* __restrict__ A = (SLOT == 0) ? g_M1 : g_M2;
    const float* __restrict__ B = (SLOT == 0) ? g_B1 : g_B2;
    float* __restrict__ C = (SLOT == 0) ? g_S1 : g_S2;
    __shared__ float As[16][64];
    __shared__ float Bs[16][64];
    int t = threadIdx.x;
    int m0 = blockIdx.x * 64;
    int tx = t & 15, ty = t >> 4;
    float acc[4][4];
#pragma unroll
    for (int i = 0; i < 4; i++)
#pragma unroll
        for (int j = 0; j < 4; j++) acc[i][j] = 0.f;
    int ar = t >> 2, ac = (t & 3) << 2;      // A: row ar (0..63), 4 floats at k-offset ac
    const float* Ap = A + (size_t)(m0 + ar) * K + ac;
    int kr = t >> 4, bc = (t & 15) << 2;     // B: k-row kr (0..15), 4 floats at col bc
    const float* Bp = B + (size_t)kr * 64 + bc;

    float4 a = *(const float4*)Ap;
    float4 b = *(const float4*)Bp;
    for (int k0 = 0; k0 < K; k0 += 16) {
        __syncthreads();
        As[ac + 0][ar] = a.x; As[ac + 1][ar] = a.y;
        As[ac + 2][ar] = a.z; As[ac + 3][ar] = a.w;
        *(float4*)&Bs[kr][bc] = b;
        __syncthreads();
        if (k0 + 16 < K) {                    // prefetch next tile
            a = *(const float4*)(Ap + k0 + 16);
            b = *(const float4*)(Bp + (size_t)(k0 + 16) * 64);
        }
#pragma unroll
        for (int kk = 0; kk < 16; kk++) {
            float4 av = *(const float4*)&As[kk][ty << 2];
            float4 bv = *(const float4*)&Bs[kk][tx << 2];
            float am[4] = {av.x, av.y, av.z, av.w};
            float bm[4] = {bv.x, bv.y, bv.z, bv.w};
#pragma unroll
            for (int i = 0; i < 4; i++)
#pragma unroll
                for (int j = 0; j < 4; j++)
                    acc[i][j] = fmaf(am[i], bm[j], acc[i][j]);
        }
    }
#pragma unroll
    for (int i = 0; i < 4; i++)
#pragma unroll
        for (int j = 0; j < 4; j++)
            C[(size_t)(m0 + (ty << 2) + i) * 64 + (tx << 2) + j] = acc[i][j];
}

// ---------- conv epilogue: out = (S + Fs@b2)/max(deg,1) + feat@root + bias ----------
template <int SLOT>
__global__ void k_apply(const float* __restrict__ feat_in, const float* __restrict__ b2,
                        const float* __restrict__ root, const float* __restrict__ bias) {
    constexpr int CIN = (SLOT == 0) ? 32 : 64;
    const float* __restrict__ S  = (SLOT == 0) ? g_S1 : g_S2;
    const float* __restrict__ Fs = (SLOT == 0) ? g_Xs : g_Hs;
    const float* __restrict__ feat = (SLOT == 0) ? feat_in : g_hnode;
    float* __restrict__ out = (SLOT == 0) ? g_out1 : g_out2;
    int n = blockIdx.x, o = threadIdx.x;
    float s = S[(size_t)n * 64 + o];
    float inv = 1.f / fmaxf((float)g_deg[n], 1.f);
    float accb = 0.f, accr = 0.f;
#pragma unroll 8
    for (int i = 0; i < CIN; i++) {
        accb = fmaf(Fs[n * CIN + i], __ldg(&b2[i * 64 + o]), accb);
        accr = fmaf(feat[(size_t)n * CIN + i], __ldg(&root[i * 64 + o]), accr);
    }
    out[(size_t)n * 64 + o] = (s + accb) * inv + accr + __ldg(&bias[o]);
}

// ---------- BN: deterministic two-pass ----------
template <int SLOT>
__global__ void k_bnstats() {
    const float* __restrict__ src = (SLOT == 0) ? g_out1 : g_out2;
    int b = blockIdx.x, c = threadIdx.x;
    int beg = b * 128, end = beg + 128; if (end > NN) end = NN;
    float s = 0.f, s2 = 0.f;
    for (int n = beg; n < end; n++) {
        float v = src[(size_t)n * 64 + c];
        s += v; s2 = fmaf(v, v, s2);
    }
    g_bnp[b * 64 + c] = s; g_bnp2[b * 64 + c] = s2;
}

template <int SLOT>
__global__ void k_bnfin(const float* __restrict__ g, const float* __restrict__ bta) {
    int c = threadIdx.x;
    float s = 0.f, s2 = 0.f;
    for (int b = 0; b < NBLK; b++) { s += g_bnp[b * 64 + c]; s2 += g_bnp2[b * 64 + c]; }
    float m = s / (float)NN;
    float v = s2 / (float)NN - m * m;
    float sc = __ldg(&g[c]) * rsqrtf(v + 1e-5f);
    g_coef[SLOT * 128 + c] = sc;
    g_coef[SLOT * 128 + 64 + c] = __ldg(&bta[c]) - m * sc;
}

template <int SLOT>
__global__ void k_bnapply() {
    const float* __restrict__ src = (SLOT == 0) ? g_out1 : g_out2;
    float* __restrict__ dst = (SLOT == 0) ? g_hnode : g_out2;  // slot1 in-place
    int n = blockIdx.x, c = threadIdx.x;
    float v = src[(size_t)n * 64 + c];
    dst[(size_t)n * 64 + c] = fmaxf(fmaf(g_coef[SLOT * 128 + c], v, g_coef[SLOT * 128 + 64 + c]), 0.f);
}

// ---------- graph pooling (batch is sorted -> binary-search segment) ----------
__global__ void k_pool(const int* __restrict__ batch) {
    int g = blockIdx.x, c = threadIdx.x;
    int lo = 0, hi = NN;
    while (lo < hi) { int mid = (lo + hi) >> 1; if (batch[mid] < g) lo = mid + 1; else hi = mid; }
    int beg = lo;
    lo = beg; hi = NN;
    while (lo < hi) { int mid = (lo + hi) >> 1; if (batch[mid] < g + 1) lo = mid + 1; else hi = mid; }
    int end = lo;
    float s = 0.f;
    for (int n = beg; n < end; n++) s += g_out2[(size_t)n * 64 + c];
    g_pool[g * 64 + c] = s;
    if (c == 0) g_pcnt[g] = (float)(end - beg);
}

// ---------- head: [mean,add] -> fc1 relu -> fc2 relu -> fc3 ----------
__global__ void k_head(const float* __restrict__ w1, const float* __restrict__ b1,
                       const float* __restrict__ w2, const float* __restrict__ b2,
                       const float* __restrict__ w3, const float* __restrict__ b3,
                       float* __restrict__ out) {
    __shared__ float gv[128], h1[64], h2[32];
    int g = blockIdx.x, t = threadIdx.x;
    float add = g_pool[g * 64 + t];
    float cnt = fmaxf(g_pcnt[g], 1.f);
    gv[t] = add / cnt; gv[64 + t] = add;
    __syncthreads();
    float a = __ldg(&b1[t]);
#pragma unroll 8
    for (int i = 0; i < 128; i++) a = fmaf(gv[i], __ldg(&w1[i * 64 + t]), a);
    h1[t] = fmaxf(a, 0.f);
    __syncthreads();
    if (t < 32) {
        float a2 = __ldg(&b2[t]);
#pragma unroll 8
        for (int i = 0; i < 64; i++) a2 = fmaf(h1[i], __ldg(&w2[i * 32 + t]), a2);
        h2[t] = fmaxf(a2, 0.f);
    }
    __syncthreads();
    if (t == 0) {
        float a3 = __ldg(&b3[0]);
#pragma unroll
        for (int i = 0; i < 32; i++) a3 = fmaf(h2[i], __ldg(&w3[i]), a3);
        out[g] = a3;
    }
}

extern "C" void kernel_launch(void* const* d_in, const int* in_sizes, int n_in,
                              void* d_out, int out_size) {
    const float* x        = (const float*)d_in[0];
    const int*   eidx     = (const int*)d_in[1];
    const float* ea       = (const float*)d_in[2];
    const int*   batch    = (const int*)d_in[3];
    const float* m1w1     = (const float*)d_in[4];
    const float* m1b1     = (const float*)d_in[5];
    const float* m1w2     = (const float*)d_in[6];
    const float* m1b2     = (const float*)d_in[7];
    const float* root1    = (const float*)d_in[8];
    const float* bias1    = (const float*)d_in[9];
    const float* bn1g     = (const float*)d_in[10];
    const float* bn1b     = (const float*)d_in[11];
    const float* m2w1     = (const float*)d_in[12];
    const float* m2b1     = (const float*)d_in[13];
    const float* m2w2     = (const float*)d_in[14];
    const float* m2b2     = (const float*)d_in[15];
    const float* root2    = (const float*)d_in[16];
    const float* bias2    = (const float*)d_in[17];
    const float* bn2g     = (const float*)d_in[18];
    const float* bn2b     = (const float*)d_in[19];
    const float* fc1w     = (const float*)d_in[20];
    const float* fc1b     = (const float*)d_in[21];
    const float* fc2w     = (const float*)d_in[22];
    const float* fc2b     = (const float*)d_in[23];
    const float* fc3w     = (const float*)d_in[24];
    const float* fc3b     = (const float*)d_in[25];
    float* out = (float*)d_out;

    const int* src = eidx;
    const int* dst = eidx + EE;

    k_zero<<<(NN + 255) / 256, 256>>>();
    k_count<<<(EE + 255) / 256, 256>>>(dst);
    k_scan<<<1, 1024>>>();
    k_fill<<<(EE + 255) / 256, 256>>>(dst);
    k_reshapeB1<<<(4096 * 64) / 256, 256>>>(m1w2);
    k_reshapeB2<<<(16384 * 64) / 256, 256>>>(m2w2);

    // conv1
    k_edge_mlp<0><<<EE, 128>>>(ea, m1w1, m1b1);
    k_buildM<0><<<NN, 128>>>(x, src);
    k_gemm<0><<<MP / 64, 256>>>();
    k_apply<0><<<NN, 64>>>(x, m1b2, root1, bias1);
    k_bnstats<0><<<NBLK, 64>>>();
    k_bnfin<0><<<1, 64>>>(bn1g, bn1b);
    k_bnapply<0><<<NN, 64>>>();

    // conv2
    k_edge_mlp<1><<<EE, 256>>>(ea, m2w1, m2b1);
    k_buildM<1><<<NN, 256>>>(nullptr, src);
    k_gemm<1><<<MP / 64, 256>>>();
    k_apply<1><<<NN, 64>>>(nullptr, m2b2, root2, bias2);
    k_bnstats<1><<<NBLK, 64>>>();
    k_bnfin<1><<<1, 64>>>(bn2g, bn2b);
    k_bnapply<1><<<NN, 64>>>();

    // pool + head
    k_pool<<<GG, 64>>>(batch);
    k_head<<<GG, 64>>>(fc1w, fc1b, fc2w, fc2b, fc3w, fc3b, out);
}

// round 6
// speedup vs baseline: 1.1512x; 1.1512x over previous
#include <cuda_runtime.h>

#define NN 20000
#define MP 20096
#define EE 50000
#define GG 128
#define NBLK 157   // ceil(NN/128) for BN partials

// ---------- device-global scratch (allocation-free rule) ----------
__device__ float g_h1[(size_t)EE * 128];
__device__ float g_h2[(size_t)EE * 256];
__device__ float g_M1[(size_t)MP * 4096];
__device__ float g_M2[(size_t)MP * 16384];
__device__ float g_B1[4096 * 64];
__device__ float g_B2[16384 * 64];
__device__ float g_P[8][(size_t)MP * 64];     // split-K partials
__device__ float g_S1[(size_t)MP * 64];
__device__ float g_S2[(size_t)MP * 64];
__device__ float g_Xs[NN * 32];
__device__ float g_Hs[NN * 64];
__device__ float g_out1[(size_t)NN * 64];
__device__ float g_hnode[(size_t)NN * 64];
__device__ float g_out2[(size_t)NN * 64];
__device__ int   g_deg[NN];
__device__ int   g_cursor[NN];
__device__ int   g_rowptr[NN];
__device__ int   g_elist[EE];
__device__ float g_bnp[NBLK * 64];
__device__ float g_bnp2[NBLK * 64];
__device__ float g_coef[4 * 64];
__device__ float g_pool[GG * 64];
__device__ float g_pcnt[GG];

__global__ void k_zero() {
    int i = blockIdx.x * blockDim.x + threadIdx.x;
    if (i < NN) { g_deg[i] = 0; g_cursor[i] = 0; }
}

// ---------- edge MLP hidden: h = relu(ea @ w1 + b1) ----------
template <int SLOT>
__global__ void k_edge_mlp(const float* __restrict__ ea, const float* __restrict__ w,
                           const float* __restrict__ b) {
    constexpr int KD = (SLOT == 0) ? 128 : 256;
    float* out = (SLOT == 0) ? g_h1 : g_h2;
    int e = blockIdx.x, t = threadIdx.x;
    float acc = __ldg(&b[t]);
#pragma unroll
    for (int c = 0; c < 8; c++)
        acc = fmaf(__ldg(&ea[e * 8 + c]), __ldg(&w[c * KD + t]), acc);
    out[(size_t)e * KD + t] = fmaxf(acc, 0.f);
}

// ---------- reshape w2 -> B[(i*KD+k)*64 + o] ----------
__global__ void k_reshapeB1(const float* __restrict__ w2) {
    int idx = blockIdx.x * blockDim.x + threadIdx.x;
    if (idx < 4096 * 64) {
        int o = idx & 63, r = idx >> 6, k = r & 127, i = r >> 7;
        g_B1[idx] = w2[k * 2048 + i * 64 + o];
    }
}
__global__ void k_reshapeB2(const float* __restrict__ w2) {
    int idx = blockIdx.x * blockDim.x + threadIdx.x;
    if (idx < 16384 * 64) {
        int o = idx & 63, r = idx >> 6, k = r & 255, i = r >> 8;
        g_B2[idx] = w2[k * 4096 + i * 64 + o];
    }
}

// ---------- CSR over dst ----------
__global__ void k_count(const int* __restrict__ dst) {
    int e = blockIdx.x * blockDim.x + threadIdx.x;
    if (e < EE) atomicAdd(&g_deg[dst[e]], 1);
}

__global__ void k_scan() {
    __shared__ int part[1024];
    int t = threadIdx.x;
    const int IT = 20;
    int base = t * IT, loc[IT], s = 0;
#pragma unroll
    for (int i = 0; i < IT; i++) {
        int idx = base + i;
        int v = (idx < NN) ? g_deg[idx] : 0;
        loc[i] = s; s += v;
    }
    part[t] = s;
    __syncthreads();
    for (int off = 1; off < 1024; off <<= 1) {
        int v = (t >= off) ? part[t - off] : 0;
        __syncthreads();
        part[t] += v;
        __syncthreads();
    }
    int prev = (t == 0) ? 0 : part[t - 1];
#pragma unroll
    for (int i = 0; i < IT; i++) {
        int idx = base + i;
        if (idx < NN) g_rowptr[idx] = prev + loc[i];
    }
}

__global__ void k_fill(const int* __restrict__ dst) {
    int e = blockIdx.x * blockDim.x + threadIdx.x;
    if (e < EE) {
        int d = dst[e];
        int p = atomicAdd(&g_cursor[d], 1);
        g_elist[g_rowptr[d] + p] = e;
    }
}

// ---------- M[n, i*KD+k] = sum_e h[e,k]*feat[src,i];  Fs[n,i] = sum_e feat[src,i] ----------
template <int SLOT>
__global__ void k_buildM(const float* __restrict__ feat_in, const int* __restrict__ src) {
    constexpr int CIN = (SLOT == 0) ? 32 : 64;
    constexpr int KD  = (SLOT == 0) ? 128 : 256;
    const float* __restrict__ h    = (SLOT == 0) ? g_h1 : g_h2;
    const float* __restrict__ feat = (SLOT == 0) ? feat_in : g_hnode;
    float* __restrict__ M  = (SLOT == 0) ? g_M1 : g_M2;
    float* __restrict__ Fs = (SLOT == 0) ? g_Xs : g_Hs;
    int n = blockIdx.x, t = threadIdx.x;
    int beg = g_rowptr[n], end = beg + g_deg[n];
    float acc[CIN];
#pragma unroll
    for (int i = 0; i < CIN; i++) acc[i] = 0.f;
    float fsum = 0.f;
    for (int p = beg; p < end; p++) {
        int e = g_elist[p];
        const float* fr = feat + (size_t)src[e] * CIN;
        float hk = h[(size_t)e * KD + t];
#pragma unroll
        for (int i = 0; i < CIN; i++) acc[i] = fmaf(hk, __ldg(&fr[i]), acc[i]);
        if (t < CIN) fsum += __ldg(&fr[t]);
    }
    float* Mrow = M + (size_t)n * (CIN * KD);
#pragma unroll
    for (int i = 0; i < CIN; i++) Mrow[i * KD + t] = acc[i];
    if (t < CIN) Fs[n * CIN + t] = fsum;
}

// ---------- split-K f32x2 GEMM: P[chunk] = A[MP,Kc] @ B[Kc,64] ----------
// BM=128, BN=64, BK=16, 128 threads, 8x8 micro via packed fma.rn.f32x2.
// A smem tile stored DUPLICATED (As2[k][2m]=As2[k][2m+1]) so broadcast pairs
// load directly as ulonglong2; B pairs are natural column adjacency.
template <int SLOT>
__global__ void __launch_bounds__(128) k_gemm() {
    constexpr int K  = (SLOT == 0) ? 4096 : 16384;
    constexpr int SK = (SLOT == 0) ? 4 : 8;
    constexpr int KC = K / SK;
    const float* __restrict__ A = (SLOT == 0) ? g_M1 : g_M2;
    const float* __restrict__ B = (SLOT == 0) ? g_B1 : g_B2;
    float* __restrict__ P = g_P[blockIdx.y];

    __shared__ float As2[16][256];
    __shared__ float Bs[16][64];

    int t = threadIdx.x;
    int m0 = blockIdx.x * 128;
    int kc0 = blockIdx.y * KC;
    int tym = t >> 3;          // 0..15 : m-group of 8 rows
    int txn = t & 7;           // 0..7  : n-group of 8 cols

    unsigned long long acc[8][4];
#pragma unroll
    for (int i = 0; i < 8; i++)
#pragma unroll
        for (int j = 0; j < 4; j++) acc[i][j] = 0ULL;

    const float* Ap = A + (size_t)(m0 + t) * K + kc0;        // thread owns A row t
    int kr = t >> 3, bc = (t & 7) << 3;                       // B: row kr, 8 cols at bc
    const float* Bp = B + (size_t)(kc0 + kr) * 64 + bc;

    float4 a0 = *(const float4*)(Ap + 0);
    float4 a1 = *(const float4*)(Ap + 4);
    float4 a2 = *(const float4*)(Ap + 8);
    float4 a3 = *(const float4*)(Ap + 12);
    float4 b0 = *(const float4*)(Bp + 0);
    float4 b1 = *(const float4*)(Bp + 4);

    for (int k0 = 0; k0 < KC; k0 += 16) {
        __syncthreads();
        {
            float va[16] = {a0.x, a0.y, a0.z, a0.w, a1.x, a1.y, a1.z, a1.w,
                            a2.x, a2.y, a2.z, a2.w, a3.x, a3.y, a3.z, a3.w};
#pragma unroll
            for (int kk = 0; kk < 16; kk++)
                *(float2*)&As2[kk][2 * t] = make_float2(va[kk], va[kk]);
            *(float4*)&Bs[kr][bc] = b0;
            *(float4*)&Bs[kr][bc + 4] = b1;
        }
        __syncthreads();
        if (k0 + 16 < KC) {
            a0 = *(const float4*)(Ap + k0 + 16);
            a1 = *(const float4*)(Ap + k0 + 20);
            a2 = *(const float4*)(Ap + k0 + 24);
            a3 = *(const float4*)(Ap + k0 + 28);
            b0 = *(const float4*)(Bp + (size_t)(k0 + 16) * 64);
            b1 = *(const float4*)(Bp + (size_t)(k0 + 16) * 64 + 4);
        }
#pragma unroll
        for (int kk = 0; kk < 16; kk++) {
            const ulonglong2* av = (const ulonglong2*)&As2[kk][tym << 4];
            const ulonglong2* bv = (const ulonglong2*)&Bs[kk][txn << 3];
            ulonglong2 p0 = av[0], p1 = av[1], p2 = av[2], p3 = av[3];
            ulonglong2 q0 = bv[0], q1 = bv[1];
            unsigned long long ap[8] = {p0.x, p0.y, p1.x, p1.y, p2.x, p2.y, p3.x, p3.y};
            unsigned long long bp[4] = {q0.x, q0.y, q1.x, q1.y};
#pragma unroll
            for (int i = 0; i < 8; i++)
#pragma unroll
                for (int j = 0; j < 4; j++)
                    asm("fma.rn.f32x2 %0, %1, %2, %0;"
                        : "+l"(acc[i][j]) : "l"(ap[i]), "l"(bp[j]));
        }
    }
#pragma unroll
    for (int i = 0; i < 8; i++) {
        float r[8];
#pragma unroll
        for (int j = 0; j < 4; j++)
            asm("mov.b64 {%0,%1}, %2;" : "=f"(r[2 * j]), "=f"(r[2 * j + 1]) : "l"(acc[i][j]));
        size_t row = (size_t)(m0 + (tym << 3) + i) * 64 + (txn << 3);
        *(float4*)&P[row]     = make_float4(r[0], r[1], r[2], r[3]);
        *(float4*)&P[row + 4] = make_float4(r[4], r[5], r[6], r[7]);
    }
}

// ---------- deterministic split-K reduce ----------
template <int SLOT>
__global__ void k_reduceS() {
    constexpr int SK = (SLOT == 0) ? 4 : 8;
    float* __restrict__ S = (SLOT == 0) ? g_S1 : g_S2;
    size_t idx = (size_t)blockIdx.x * blockDim.x + threadIdx.x;
    if (idx < (size_t)MP * 64) {
        float s = 0.f;
#pragma unroll
        for (int c = 0; c < SK; c++) s += g_P[c][idx];
        S[idx] = s;
    }
}

// ---------- conv epilogue: out = (S + Fs@b2)/max(deg,1) + feat@root + bias ----------
template <int SLOT>
__global__ void k_apply(const float* __restrict__ feat_in, const float* __restrict__ b2,
                        const float* __restrict__ root, const float* __restrict__ bias) {
    constexpr int CIN = (SLOT == 0) ? 32 : 64;
    const float* __restrict__ S  = (SLOT == 0) ? g_S1 : g_S2;
    const float* __restrict__ Fs = (SLOT == 0) ? g_Xs : g_Hs;
    const float* __restrict__ feat = (SLOT == 0) ? feat_in : g_hnode;
    float* __restrict__ out = (SLOT == 0) ? g_out1 : g_out2;
    int n = blockIdx.x, o = threadIdx.x;
    float s = S[(size_t)n * 64 + o];
    float inv = 1.f / fmaxf((float)g_deg[n], 1.f);
    float accb = 0.f, accr = 0.f;
#pragma unroll 8
    for (int i = 0; i < CIN; i++) {
        accb = fmaf(Fs[n * CIN + i], __ldg(&b2[i * 64 + o]), accb);
        accr = fmaf(feat[(size_t)n * CIN + i], __ldg(&root[i * 64 + o]), accr);
    }
    out[(size_t)n * 64 + o] = (s + accb) * inv + accr + __ldg(&bias[o]);
}

// ---------- BN: deterministic two-pass ----------
template <int SLOT>
__global__ void k_bnstats() {
    const float* __restrict__ src = (SLOT == 0) ? g_out1 : g_out2;
    int b = blockIdx.x, c = threadIdx.x;
    int beg = b * 128, end = beg + 128; if (end > NN) end = NN;
    float s = 0.f, s2 = 0.f;
    for (int n = beg; n < end; n++) {
        float v = src[(size_t)n * 64 + c];
        s += v; s2 = fmaf(v, v, s2);
    }
    g_bnp[b * 64 + c] = s; g_bnp2[b * 64 + c] = s2;
}

template <int SLOT>
__global__ void k_bnfin(const float* __restrict__ g, const float* __restrict__ bta) {
    int c = threadIdx.x;
    float s = 0.f, s2 = 0.f;
    for (int b = 0; b < NBLK; b++) { s += g_bnp[b * 64 + c]; s2 += g_bnp2[b * 64 + c]; }
    float m = s / (float)NN;
    float v = s2 / (float)NN - m * m;
    float sc = __ldg(&g[c]) * rsqrtf(v + 1e-5f);
    g_coef[SLOT * 128 + c] = sc;
    g_coef[SLOT * 128 + 64 + c] = __ldg(&bta[c]) - m * sc;
}

template <int SLOT>
__global__ void k_bnapply() {
    const float* __restrict__ src = (SLOT == 0) ? g_out1 : g_out2;
    float* __restrict__ dst = (SLOT == 0) ? g_hnode : g_out2;
    int n = blockIdx.x, c = threadIdx.x;
    float v = src[(size_t)n * 64 + c];
    dst[(size_t)n * 64 + c] = fmaxf(fmaf(g_coef[SLOT * 128 + c], v, g_coef[SLOT * 128 + 64 + c]), 0.f);
}

// ---------- graph pooling (batch sorted -> binary-search segment) ----------
__global__ void k_pool(const int* __restrict__ batch) {
    int g = blockIdx.x, c = threadIdx.x;
    int lo = 0, hi = NN;
    while (lo < hi) { int mid = (lo + hi) >> 1; if (batch[mid] < g) lo = mid + 1; else hi = mid; }
    int beg = lo;
    lo = beg; hi = NN;
    while (lo < hi) { int mid = (lo + hi) >> 1; if (batch[mid] < g + 1) lo = mid + 1; else hi = mid; }
    int end = lo;
    float s = 0.f;
    for (int n = beg; n < end; n++) s += g_out2[(size_t)n * 64 + c];
    g_pool[g * 64 + c] = s;
    if (c == 0) g_pcnt[g] = (float)(end - beg);
}

// ---------- head ----------
__global__ void k_head(const float* __restrict__ w1, const float* __restrict__ b1,
                       const float* __restrict__ w2, const float* __restrict__ b2,
                       const float* __restrict__ w3, const float* __restrict__ b3,
                       float* __restrict__ out) {
    __shared__ float gv[128], h1[64], h2[32];
    int g = blockIdx.x, t = threadIdx.x;
    float add = g_pool[g * 64 + t];
    float cnt = fmaxf(g_pcnt[g], 1.f);
    gv[t] = add / cnt; gv[64 + t] = add;
    __syncthreads();
    float a = __ldg(&b1[t]);
#pragma unroll 8
    for (int i = 0; i < 128; i++) a = fmaf(gv[i], __ldg(&w1[i * 64 + t]), a);
    h1[t] = fmaxf(a, 0.f);
    __syncthreads();
    if (t < 32) {
        float a2 = __ldg(&b2[t]);
#pragma unroll 8
        for (int i = 0; i < 64; i++) a2 = fmaf(h1[i], __ldg(&w2[i * 32 + t]), a2);
        h2[t] = fmaxf(a2, 0.f);
    }
    __syncthreads();
    if (t == 0) {
        float a3 = __ldg(&b3[0]);
#pragma unroll
        for (int i = 0; i < 32; i++) a3 = fmaf(h2[i], __ldg(&w3[i]), a3);
        out[g] = a3;
    }
}

extern "C" void kernel_launch(void* const* d_in, const int* in_sizes, int n_in,
                              void* d_out, int out_size) {
    const float* x     = (const float*)d_in[0];
    const int*   eidx  = (const int*)d_in[1];
    const float* ea    = (const float*)d_in[2];
    const int*   batch = (const int*)d_in[3];
    const float* m1w1  = (const float*)d_in[4];
    const float* m1b1  = (const float*)d_in[5];
    const float* m1w2  = (const float*)d_in[6];
    const float* m1b2  = (const float*)d_in[7];
    const float* root1 = (const float*)d_in[8];
    const float* bias1 = (const float*)d_in[9];
    const float* bn1g  = (const float*)d_in[10];
    const float* bn1b  = (const float*)d_in[11];
    const float* m2w1  = (const float*)d_in[12];
    const float* m2b1  = (const float*)d_in[13];
    const float* m2w2  = (const float*)d_in[14];
    const float* m2b2  = (const float*)d_in[15];
    const float* root2 = (const float*)d_in[16];
    const float* bias2 = (const float*)d_in[17];
    const float* bn2g  = (const float*)d_in[18];
    const float* bn2b  = (const float*)d_in[19];
    const float* fc1w  = (const float*)d_in[20];
    const float* fc1b  = (const float*)d_in[21];
    const float* fc2w  = (const float*)d_in[22];
    const float* fc2b  = (const float*)d_in[23];
    const float* fc3w  = (const float*)d_in[24];
    const float* fc3b  = (const float*)d_in[25];
    float* out = (float*)d_out;

    const int* src = eidx;
    const int* dst = eidx + EE;

    k_zero<<<(NN + 255) / 256, 256>>>();
    k_count<<<(EE + 255) / 256, 256>>>(dst);
    k_scan<<<1, 1024>>>();
    k_fill<<<(EE + 255) / 256, 256>>>(dst);
    k_reshapeB1<<<(4096 * 64) / 256, 256>>>(m1w2);
    k_reshapeB2<<<(16384 * 64) / 256, 256>>>(m2w2);

    // conv1
    k_edge_mlp<0><<<EE, 128>>>(ea, m1w1, m1b1);
    k_buildM<0><<<NN, 128>>>(x, src);
    k_gemm<0><<<dim3(MP / 128, 4), 128>>>();
    k_reduceS<0><<<((size_t)MP * 64 + 255) / 256, 256>>>();
    k_apply<0><<<NN, 64>>>(x, m1b2, root1, bias1);
    k_bnstats<0><<<NBLK, 64>>>();
    k_bnfin<0><<<1, 64>>>(bn1g, bn1b);
    k_bnapply<0><<<NN, 64>>>();

    // conv2
    k_edge_mlp<1><<<EE, 256>>>(ea, m2w1, m2b1);
    k_buildM<1><<<NN, 256>>>(nullptr, src);
    k_gemm<1><<<dim3(MP / 128, 8), 128>>>();
    k_reduceS<1><<<((size_t)MP * 64 + 255) / 256, 256>>>();
    k_apply<1><<<NN, 64>>>(nullptr, m2b2, root2, bias2);
    k_bnstats<1><<<NBLK, 64>>>();
    k_bnfin<1><<<1, 64>>>(bn2g, bn2b);
    k_bnapply<1><<<NN, 64>>>();

    // pool + head
    k_pool<<<GG, 64>>>(batch);
    k_head<<<GG, 64>>>(fc1w, fc1b, fc2w, fc2b, fc3w, fc3b, out);
}

// round 8
// speedup vs baseline: 2.1744x; 1.8887x over previous
#include <cuda_runtime.h>
#include <cuda_bf16.h>

#define NN 20000
#define MP 20096
#define EE 50000
#define GG 128
#define NBLK 157   // ceil(NN/128) for BN partials

// ---------- device-global scratch (allocation-free rule) ----------
__device__ float g_h1[(size_t)EE * 128];
__device__ float g_h2[(size_t)EE * 256];
__device__ __nv_bfloat16 g_M1h[(size_t)MP * 4096];
__device__ __nv_bfloat16 g_M1l[(size_t)MP * 4096];
__device__ __nv_bfloat16 g_M2h[(size_t)MP * 16384];
__device__ __nv_bfloat16 g_M2l[(size_t)MP * 16384];
__device__ __nv_bfloat16 g_B1h[64 * 4096];
__device__ __nv_bfloat16 g_B1l[64 * 4096];
__device__ __nv_bfloat16 g_B2h[64 * 16384];
__device__ __nv_bfloat16 g_B2l[64 * 16384];
__device__ float g_P[4][(size_t)MP * 64];     // split-K partials
__device__ float g_S1[(size_t)MP * 64];
__device__ float g_S2[(size_t)MP * 64];
__device__ float g_Xs[NN * 32];
__device__ float g_Hs[NN * 64];
__device__ float g_out1[(size_t)NN * 64];
__device__ float g_hnode[(size_t)NN * 64];
__device__ float g_out2[(size_t)NN * 64];
__device__ int   g_deg[NN];
__device__ int   g_cursor[NN];
__device__ int   g_rowptr[NN];
__device__ int   g_elist[EE];
__device__ float g_bnp[NBLK * 64];
__device__ float g_bnp2[NBLK * 64];
__device__ float g_coef[4 * 64];
__device__ float g_pool[GG * 64];
__device__ float g_pcnt[GG];

// ---------- PTX helpers (generic sm_100-safe: ldmatrix / mma.sync / cp.async) ----------
__device__ __forceinline__ unsigned smem_u32(const void* p) {
    unsigned r;
    asm("{ .reg .u64 t; cvta.to.shared.u64 t, %1; cvt.u32.u64 %0, t; }" : "=r"(r) : "l"(p));
    return r;
}

__device__ __forceinline__ void ldsm4(unsigned r[4], unsigned addr) {
    asm volatile("ldmatrix.sync.aligned.m8n8.x4.shared.b16 {%0,%1,%2,%3}, [%4];"
                 : "=r"(r[0]), "=r"(r[1]), "=r"(r[2]), "=r"(r[3]) : "r"(addr));
}

__device__ __forceinline__ void cpa(unsigned dst, const void* src) {
    asm volatile("cp.async.cg.shared.global [%0], [%1], 16;" :: "r"(dst), "l"(src));
}

#define MMA_BF16(c, a, b) \
    asm volatile("mma.sync.aligned.m16n8k16.row.col.f32.bf16.bf16.f32 " \
                 "{%0,%1,%2,%3}, {%4,%5,%6,%7}, {%8,%9}, {%0,%1,%2,%3};" \
                 : "+f"((c)[0]), "+f"((c)[1]), "+f"((c)[2]), "+f"((c)[3]) \
                 : "r"((a)[0]), "r"((a)[1]), "r"((a)[2]), "r"((a)[3]), \
                   "r"((b)[0]), "r"((b)[1]))

__global__ void k_zero() {
    int i = blockIdx.x * blockDim.x + threadIdx.x;
    if (i < NN) { g_deg[i] = 0; g_cursor[i] = 0; }
}

// ---------- edge MLP hidden: h = relu(ea @ w1 + b1) ----------
template <int SLOT>
__global__ void k_edge_mlp(const float* __restrict__ ea, const float* __restrict__ w,
                           const float* __restrict__ b) {
    constexpr int KD = (SLOT == 0) ? 128 : 256;
    float* out = (SLOT == 0) ? g_h1 : g_h2;
    int e = blockIdx.x, t = threadIdx.x;
    float acc = __ldg(&b[t]);
#pragma unroll
    for (int c = 0; c < 8; c++)
        acc = fmaf(__ldg(&ea[e * 8 + c]), __ldg(&w[c * KD + t]), acc);
    out[(size_t)e * KD + t] = fmaxf(acc, 0.f);
}

// ---------- reshape w2 -> Bt[o][i*KD+k] = w2[k, i*64+o], bf16 hi/lo ----------
__global__ void k_reshapeB1(const float* __restrict__ w2) {
    int idx = blockIdx.x * blockDim.x + threadIdx.x;
    if (idx < 64 * 4096) {
        int o = idx >> 12, c = idx & 4095;
        int i = c >> 7, k = c & 127;
        float v = w2[k * 2048 + i * 64 + o];
        __nv_bfloat16 hv = __float2bfloat16(v);
        g_B1h[idx] = hv;
        g_B1l[idx] = __float2bfloat16(v - __bfloat162float(hv));
    }
}
__global__ void k_reshapeB2(const float* __restrict__ w2) {
    int idx = blockIdx.x * blockDim.x + threadIdx.x;
    if (idx < 64 * 16384) {
        int o = idx >> 14, c = idx & 16383;
        int i = c >> 8, k = c & 255;
        float v = w2[k * 4096 + i * 64 + o];
        __nv_bfloat16 hv = __float2bfloat16(v);
        g_B2h[idx] = hv;
        g_B2l[idx] = __float2bfloat16(v - __bfloat162float(hv));
    }
}

// ---------- CSR over dst ----------
__global__ void k_count(const int* __restrict__ dst) {
    int e = blockIdx.x * blockDim.x + threadIdx.x;
    if (e < EE) atomicAdd(&g_deg[dst[e]], 1);
}

__global__ void k_scan() {
    __shared__ int part[1024];
    int t = threadIdx.x;
    const int IT = 20;
    int base = t * IT, loc[IT], s = 0;
#pragma unroll
    for (int i = 0; i < IT; i++) {
        int idx = base + i;
        int v = (idx < NN) ? g_deg[idx] : 0;
        loc[i] = s; s += v;
    }
    part[t] = s;
    __syncthreads();
    for (int off = 1; off < 1024; off <<= 1) {
        int v = (t >= off) ? part[t - off] : 0;
        __syncthreads();
        part[t] += v;
        __syncthreads();
    }
    int prev = (t == 0) ? 0 : part[t - 1];
#pragma unroll
    for (int i = 0; i < IT; i++) {
        int idx = base + i;
        if (idx < NN) g_rowptr[idx] = prev + loc[i];
    }
}

__global__ void k_fill(const int* __restrict__ dst) {
    int e = blockIdx.x * blockDim.x + threadIdx.x;
    if (e < EE) {
        int d = dst[e];
        int p = atomicAdd(&g_cursor[d], 1);
        g_elist[g_rowptr[d] + p] = e;
    }
}

// ---------- M[n, i*KD+k] = sum_e h[e,k]*feat[src,i] (bf16 hi/lo);  Fs[n,i] = sum feat ----------
template <int SLOT>
__global__ void k_buildM(const float* __restrict__ feat_in, const int* __restrict__ src) {
    constexpr int CIN = (SLOT == 0) ? 32 : 64;
    constexpr int KD  = (SLOT == 0) ? 128 : 256;
    const float* __restrict__ h    = (SLOT == 0) ? g_h1 : g_h2;
    const float* __restrict__ feat = (SLOT == 0) ? feat_in : g_hnode;
    __nv_bfloat16* __restrict__ Mh = (SLOT == 0) ? g_M1h : g_M2h;
    __nv_bfloat16* __restrict__ Ml = (SLOT == 0) ? g_M1l : g_M2l;
    float* __restrict__ Fs = (SLOT == 0) ? g_Xs : g_Hs;
    int n = blockIdx.x, t = threadIdx.x;
    int beg = g_rowptr[n], end = beg + g_deg[n];
    float acc[CIN];
#pragma unroll
    for (int i = 0; i < CIN; i++) acc[i] = 0.f;
    float fsum = 0.f;
    for (int p = beg; p < end; p++) {
        int e = g_elist[p];
        const float* fr = feat + (size_t)src[e] * CIN;
        float hk = h[(size_t)e * KD + t];
#pragma unroll
        for (int i = 0; i < CIN; i++) acc[i] = fmaf(hk, __ldg(&fr[i]), acc[i]);
        if (t < CIN) fsum += __ldg(&fr[t]);
    }
    size_t rowb = (size_t)n * (CIN * KD);
#pragma unroll
    for (int i = 0; i < CIN; i++) {
        float v = acc[i];
        __nv_bfloat16 hv = __float2bfloat16(v);
        Mh[rowb + i * KD + t] = hv;
        Ml[rowb + i * KD + t] = __float2bfloat16(v - __bfloat162float(hv));
    }
    if (t < CIN) Fs[n * CIN + t] = fsum;
}

// ---------- warp-HMMA bf16x3 GEMM, split-K x4 ----------
// C[MP,64] = A[MP,K] @ Bt[64,K]^T,  S = Ah*Bh + Al*Bh + Ah*Bl (fp32 acc).
// BM=128 (4 warps x m32), BK=32, 80B-padded smem rows (conflict-free LDSM),
// cp.async double buffer. mma.sync m16n8k16 row.col: Bt[n][k] row-major IS the col operand.
// stage layout: Ah 0..10240, Al 10240.., Bh 20480.., Bl 25600..; stage size 30720.
#define STG 30720
#define SMEM_GEMM (2 * STG)
template <int SLOT>
__global__ void __launch_bounds__(128) k_gemm_hmma() {
    constexpr int K  = (SLOT == 0) ? 4096 : 16384;
    constexpr int KC = K / 4;
    constexpr int ITERS = KC / 32;
    const __nv_bfloat16* __restrict__ Ah = (SLOT == 0) ? g_M1h : g_M2h;
    const __nv_bfloat16* __restrict__ Al = (SLOT == 0) ? g_M1l : g_M2l;
    const __nv_bfloat16* __restrict__ Bh = (SLOT == 0) ? g_B1h : g_B2h;
    const __nv_bfloat16* __restrict__ Bl = (SLOT == 0) ? g_B1l : g_B2l;

    extern __shared__ char smem[];
    unsigned sb = smem_u32(smem);
    const int tid = threadIdx.x, lid = tid & 31, w = tid >> 5;
    const int m0 = blockIdx.x * 128;
    const int kc0 = blockIdx.y * KC;
    float* __restrict__ P = g_P[blockIdx.y];

    // cp.async geometry: A tile 128 rows x 64B (4 x 16B chunks), B tile 64 rows x 64B
    unsigned dA[4]; const __nv_bfloat16 *sAh[4], *sAl[4];
#pragma unroll
    for (int j = 0; j < 4; j++) {
        int c = tid + 128 * j, row = c >> 2, o = c & 3;
        dA[j] = row * 80 + o * 16;
        sAh[j] = Ah + (size_t)(m0 + row) * K + kc0 + o * 8;
        sAl[j] = Al + (size_t)(m0 + row) * K + kc0 + o * 8;
    }
    unsigned dB[2]; const __nv_bfloat16 *sBh[2], *sBl[2];
#pragma unroll
    for (int j = 0; j < 2; j++) {
        int c = tid + 128 * j, row = c >> 2, o = c & 3;
        dB[j] = row * 80 + o * 16;
        sBh[j] = Bh + (size_t)row * K + kc0 + o * 8;
        sBl[j] = Bl + (size_t)row * K + kc0 + o * 8;
    }

    float acc[2][8][4];
#pragma unroll
    for (int mt = 0; mt < 2; mt++)
#pragma unroll
        for (int nt = 0; nt < 8; nt++)
#pragma unroll
            for (int r = 0; r < 4; r++) acc[mt][nt][r] = 0.f;

    // prologue: stage 0 <- iter 0
#pragma unroll
    for (int j = 0; j < 4; j++) { cpa(sb + dA[j], sAh[j]); cpa(sb + 10240 + dA[j], sAl[j]); }
#pragma unroll
    for (int j = 0; j < 2; j++) { cpa(sb + 20480 + dB[j], sBh[j]); cpa(sb + 25600 + dB[j], sBl[j]); }
    asm volatile("cp.async.commit_group;" ::: "memory");

    // LDSM lane addressing (constant per thread)
    const unsigned aLane = (unsigned)((lid & 15) * 80 + ((lid >> 4) << 3) * 2);
    const unsigned bLane = (unsigned)(((lid & 7) + ((lid & 16) ? 8 : 0)) * 80 + ((lid & 8) ? 16 : 0));

    for (int it = 0; it < ITERS; it++) {
        if (it + 1 < ITERS) {
            unsigned s2 = sb + ((it + 1) & 1) * STG;
            int ko = (it + 1) * 32;
#pragma unroll
            for (int j = 0; j < 4; j++) { cpa(s2 + dA[j], sAh[j] + ko); cpa(s2 + 10240 + dA[j], sAl[j] + ko); }
#pragma unroll
            for (int j = 0; j < 2; j++) { cpa(s2 + 20480 + dB[j], sBh[j] + ko); cpa(s2 + 25600 + dB[j], sBl[j] + ko); }
            asm volatile("cp.async.commit_group;" ::: "memory");
            asm volatile("cp.async.wait_group 1;" ::: "memory");
        } else {
            asm volatile("cp.async.wait_group 0;" ::: "memory");
        }
        __syncthreads();
        unsigned s1 = sb + (it & 1) * STG;
#pragma unroll
        for (int kk = 0; kk < 32; kk += 16) {
            unsigned ah[2][4], al[2][4];
#pragma unroll
            for (int mt = 0; mt < 2; mt++) {
                unsigned ra = s1 + (unsigned)((w * 32 + mt * 16) * 80 + kk * 2) + aLane;
                ldsm4(ah[mt], ra);
                ldsm4(al[mt], ra + 10240);
            }
            unsigned bh[4][4], bl[4][4];
#pragma unroll
            for (int ng = 0; ng < 4; ng++) {
                unsigned rb = s1 + 20480 + (unsigned)(ng * 16 * 80 + kk * 2) + bLane;
                ldsm4(bh[ng], rb);
                ldsm4(bl[ng], rb + 5120);
            }
#pragma unroll
            for (int mt = 0; mt < 2; mt++)
#pragma unroll
                for (int nt = 0; nt < 8; nt++) {
                    unsigned* fh = &bh[nt >> 1][(nt & 1) * 2];
                    unsigned* fl = &bl[nt >> 1][(nt & 1) * 2];
                    MMA_BF16(acc[mt][nt], ah[mt], fh);
                    MMA_BF16(acc[mt][nt], al[mt], fh);
                    MMA_BF16(acc[mt][nt], ah[mt], fl);
                }
        }
        __syncthreads();
    }

    // epilogue: write fp32 partials
#pragma unroll
    for (int mt = 0; mt < 2; mt++) {
        int rg = m0 + w * 32 + mt * 16 + (lid >> 2);
#pragma unroll
        for (int nt = 0; nt < 8; nt++) {
            int col = nt * 8 + (lid & 3) * 2;
            *(float2*)&P[(size_t)rg * 64 + col]       = make_float2(acc[mt][nt][0], acc[mt][nt][1]);
            *(float2*)&P[(size_t)(rg + 8) * 64 + col] = make_float2(acc[mt][nt][2], acc[mt][nt][3]);
        }
    }
}

// ---------- deterministic split-K reduce ----------
template <int SLOT>
__global__ void k_reduceS() {
    float* __restrict__ S = (SLOT == 0) ? g_S1 : g_S2;
    size_t idx = (size_t)blockIdx.x * blockDim.x + threadIdx.x;
    if (idx < (size_t)MP * 64) {
        float s = 0.f;
#pragma unroll
        for (int c = 0; c < 4; c++) s += g_P[c][idx];
        S[idx] = s;
    }
}

// ---------- conv epilogue: out = (S + Fs@b2)/max(deg,1) + feat@root + bias ----------
template <int SLOT>
__global__ void k_apply(const float* __restrict__ feat_in, const float* __restrict__ b2,
                        const float* __restrict__ root, const float* __restrict__ bias) {
    constexpr int CIN = (SLOT == 0) ? 32 : 64;
    const float* __restrict__ S  = (SLOT == 0) ? g_S1 : g_S2;
    const float* __restrict__ Fs = (SLOT == 0) ? g_Xs : g_Hs;
    const float* __restrict__ feat = (SLOT == 0) ? feat_in : g_hnode;
    float* __restrict__ out = (SLOT == 0) ? g_out1 : g_out2;
    int n = blockIdx.x, o = threadIdx.x;
    float s = S[(size_t)n * 64 + o];
    float inv = 1.f / fmaxf((float)g_deg[n], 1.f);
    float accb = 0.f, accr = 0.f;
#pragma unroll 8
    for (int i = 0; i < CIN; i++) {
        accb = fmaf(Fs[n * CIN + i], __ldg(&b2[i * 64 + o]), accb);
        accr = fmaf(feat[(size_t)n * CIN + i], __ldg(&root[i * 64 + o]), accr);
    }
    out[(size_t)n * 64 + o] = (s + accb) * inv + accr + __ldg(&bias[o]);
}

// ---------- BN: deterministic two-pass ----------
template <int SLOT>
__global__ void k_bnstats() {
    const float* __restrict__ src = (SLOT == 0) ? g_out1 : g_out2;
    int b = blockIdx.x, c = threadIdx.x;
    int beg = b * 128, end = beg + 128; if (end > NN) end = NN;
    float s = 0.f, s2 = 0.f;
    for (int n = beg; n < end; n++) {
        float v = src[(size_t)n * 64 + c];
        s += v; s2 = fmaf(v, v, s2);
    }
    g_bnp[b * 64 + c] = s; g_bnp2[b * 64 + c] = s2;
}

template <int SLOT>
__global__ void k_bnfin(const float* __restrict__ g, const float* __restrict__ bta) {
    int c = threadIdx.x;
    float s = 0.f, s2 = 0.f;
    for (int b = 0; b < NBLK; b++) { s += g_bnp[b * 64 + c]; s2 += g_bnp2[b * 64 + c]; }
    float m = s / (float)NN;
    float v = s2 / (float)NN - m * m;
    float sc = __ldg(&g[c]) * rsqrtf(v + 1e-5f);
    g_coef[SLOT * 128 + c] = sc;
    g_coef[SLOT * 128 + 64 + c] = __ldg(&bta[c]) - m * sc;
}

template <int SLOT>
__global__ void k_bnapply() {
    const float* __restrict__ src = (SLOT == 0) ? g_out1 : g_out2;
    float* __restrict__ dst = (SLOT == 0) ? g_hnode : g_out2;
    int n = blockIdx.x, c = threadIdx.x;
    float v = src[(size_t)n * 64 + c];
    dst[(size_t)n * 64 + c] = fmaxf(fmaf(g_coef[SLOT * 128 + c], v, g_coef[SLOT * 128 + 64 + c]), 0.f);
}

// ---------- graph pooling (batch sorted -> binary-search segment) ----------
__global__ void k_pool(const int* __restrict__ batch) {
    int g = blockIdx.x, c = threadIdx.x;
    int lo = 0, hi = NN;
    while (lo < hi) { int mid = (lo + hi) >> 1; if (batch[mid] < g) lo = mid + 1; else hi = mid; }
    int beg = lo;
    lo = beg; hi = NN;
    while (lo < hi) { int mid = (lo + hi) >> 1; if (batch[mid] < g + 1) lo = mid + 1; else hi = mid; }
    int end = lo;
    float s = 0.f;
    for (int n = beg; n < end; n++) s += g_out2[(size_t)n * 64 + c];
    g_pool[g * 64 + c] = s;
    if (c == 0) g_pcnt[g] = (float)(end - beg);
}

// ---------- head ----------
__global__ void k_head(const float* __restrict__ w1, const float* __restrict__ b1,
                       const float* __restrict__ w2, const float* __restrict__ b2,
                       const float* __restrict__ w3, const float* __restrict__ b3,
                       float* __restrict__ out) {
    __shared__ float gv[128], h1[64], h2[32];
    int g = blockIdx.x, t = threadIdx.x;
    float add = g_pool[g * 64 + t];
    float cnt = fmaxf(g_pcnt[g], 1.f);
    gv[t] = add / cnt; gv[64 + t] = add;
    __syncthreads();
    float a = __ldg(&b1[t]);
#pragma unroll 8
    for (int i = 0; i < 128; i++) a = fmaf(gv[i], __ldg(&w1[i * 64 + t]), a);
    h1[t] = fmaxf(a, 0.f);
    __syncthreads();
    if (t < 32) {
        float a2 = __ldg(&b2[t]);
#pragma unroll 8
        for (int i = 0; i < 64; i++) a2 = fmaf(h1[i], __ldg(&w2[i * 32 + t]), a2);
        h2[t] = fmaxf(a2, 0.f);
    }
    __syncthreads();
    if (t == 0) {
        float a3 = __ldg(&b3[0]);
#pragma unroll
        for (int i = 0; i < 32; i++) a3 = fmaf(h2[i], __ldg(&w3[i]), a3);
        out[g] = a3;
    }
}

extern "C" void kernel_launch(void* const* d_in, const int* in_sizes, int n_in,
                              void* d_out, int out_size) {
    const float* x     = (const float*)d_in[0];
    const int*   eidx  = (const int*)d_in[1];
    const float* ea    = (const float*)d_in[2];
    const int*   batch = (const int*)d_in[3];
    const float* m1w1  = (const float*)d_in[4];
    const float* m1b1  = (const float*)d_in[5];
    const float* m1w2  = (const float*)d_in[6];
    const float* m1b2  = (const float*)d_in[7];
    const float* root1 = (const float*)d_in[8];
    const float* bias1 = (const float*)d_in[9];
    const float* bn1g  = (const float*)d_in[10];
    const float* bn1b  = (const float*)d_in[11];
    const float* m2w1  = (const float*)d_in[12];
    const float* m2b1  = (const float*)d_in[13];
    const float* m2w2  = (const float*)d_in[14];
    const float* m2b2  = (const float*)d_in[15];
    const float* root2 = (const float*)d_in[16];
    const float* bias2 = (const float*)d_in[17];
    const float* bn2g  = (const float*)d_in[18];
    const float* bn2b  = (const float*)d_in[19];
    const float* fc1w  = (const float*)d_in[20];
    const float* fc1b  = (const float*)d_in[21];
    const float* fc2w  = (const float*)d_in[22];
    const float* fc2b  = (const float*)d_in[23];
    const float* fc3w  = (const float*)d_in[24];
    const float* fc3b  = (const float*)d_in[25];
    float* out = (float*)d_out;

    const int* src = eidx;
    const int* dst = eidx + EE;

    cudaFuncSetAttribute(k_gemm_hmma<0>, cudaFuncAttributeMaxDynamicSharedMemorySize, SMEM_GEMM);
    cudaFuncSetAttribute(k_gemm_hmma<1>, cudaFuncAttributeMaxDynamicSharedMemorySize, SMEM_GEMM);

    k_zero<<<(NN + 255) / 256, 256>>>();
    k_count<<<(EE + 255) / 256, 256>>>(dst);
    k_scan<<<1, 1024>>>();
    k_fill<<<(EE + 255) / 256, 256>>>(dst);
    k_reshapeB1<<<(64 * 4096) / 256, 256>>>(m1w2);
    k_reshapeB2<<<(64 * 16384) / 256, 256>>>(m2w2);

    // conv1
    k_edge_mlp<0><<<EE, 128>>>(ea, m1w1, m1b1);
    k_buildM<0><<<NN, 128>>>(x, src);
    k_gemm_hmma<0><<<dim3(MP / 128, 4), 128, SMEM_GEMM>>>();
    k_reduceS<0><<<((size_t)MP * 64 + 255) / 256, 256>>>();
    k_apply<0><<<NN, 64>>>(x, m1b2, root1, bias1);
    k_bnstats<0><<<NBLK, 64>>>();
    k_bnfin<0><<<1, 64>>>(bn1g, bn1b);
    k_bnapply<0><<<NN, 64>>>();

    // conv2
    k_edge_mlp<1><<<EE, 256>>>(ea, m2w1, m2b1);
    k_buildM<1><<<NN, 256>>>(nullptr, src);
    k_gemm_hmma<1><<<dim3(MP / 128, 4), 128, SMEM_GEMM>>>();
    k_reduceS<1><<<((size_t)MP * 64 + 255) / 256, 256>>>();
    k_apply<1><<<NN, 64>>>(nullptr, m2b2, root2, bias2);
    k_bnstats<1><<<NBLK, 64>>>();
    k_bnfin<1><<<1, 64>>>(bn2g, bn2b);
    k_bnapply<1><<<NN, 64>>>();

    // pool + head
    k_pool<<<GG, 64>>>(batch);
    k_head<<<GG, 64>>>(fc1w, fc1b, fc2w, fc2b, fc3w, fc3b, out);
}